// round 1
// baseline (speedup 1.0000x reference)
#include <cuda_runtime.h>
#include <math_constants.h>

#define B   32
#define C   256
#define HW  4096          // 64*64
#define HID 16

// scratch (allocation-free rule: __device__ globals)
__device__ float g_avg [B*C];
__device__ float g_max [B*C];
__device__ float g_catt[B*C];
__device__ float g_spavg[B*HW];
__device__ float g_spmax[B*HW];
__device__ float g_asig [B*HW];

// ---------------------------------------------------------------------------
// k1: per-(b,c) mean & max over 4096 pixels. 8192 blocks x 256 thr, float4.
// Reads x FORWARD.
// ---------------------------------------------------------------------------
__global__ void k_chanstats(const float* __restrict__ x) {
    int bc = blockIdx.x;                       // 0..8191
    const float4* xp = (const float4*)x + (size_t)bc * 1024;
    float s = 0.f, m = -CUDART_INF_F;
#pragma unroll
    for (int k = 0; k < 4; k++) {
        float4 v = xp[k * 256 + threadIdx.x];
        s += (v.x + v.y) + (v.z + v.w);
        m = fmaxf(m, fmaxf(fmaxf(v.x, v.y), fmaxf(v.z, v.w)));
    }
#pragma unroll
    for (int off = 16; off; off >>= 1) {
        s += __shfl_down_sync(0xffffffffu, s, off);
        m = fmaxf(m, __shfl_down_sync(0xffffffffu, m, off));
    }
    __shared__ float ss[8], sm[8];
    if ((threadIdx.x & 31) == 0) { ss[threadIdx.x >> 5] = s; sm[threadIdx.x >> 5] = m; }
    __syncthreads();
    if (threadIdx.x == 0) {
        float S = 0.f, M = -CUDART_INF_F;
#pragma unroll
        for (int i = 0; i < 8; i++) { S += ss[i]; M = fmaxf(M, sm[i]); }
        g_avg[bc] = S * (1.f / 4096.f);
        g_max[bc] = M;
    }
}

// ---------------------------------------------------------------------------
// k2: channel MLP + sigmoid. 32 blocks (one per batch) x 256 thr. Tiny.
// ch_att = sigmoid( w2 @ ( relu(w1@avg) + relu(w1@max) ) )
// ---------------------------------------------------------------------------
__global__ void k_mlp(const float* __restrict__ w1, const float* __restrict__ w2) {
    int b = blockIdx.x;
    __shared__ float s_avg[C], s_mx[C], s_h[HID];
    s_avg[threadIdx.x] = g_avg[b * C + threadIdx.x];
    s_mx [threadIdx.x] = g_max[b * C + threadIdx.x];
    __syncthreads();

    int r    = threadIdx.x >> 4;   // hidden unit 0..15
    int lane = threadIdx.x & 15;
    float pa = 0.f, pm = 0.f;
#pragma unroll
    for (int j = 0; j < 16; j++) {
        int c = lane + j * 16;
        float w = w1[r * C + c];
        pa += w * s_avg[c];
        pm += w * s_mx[c];
    }
#pragma unroll
    for (int off = 8; off; off >>= 1) {
        pa += __shfl_down_sync(0xffffffffu, pa, off, 16);
        pm += __shfl_down_sync(0xffffffffu, pm, off, 16);
    }
    if (lane == 0) s_h[r] = fmaxf(pa, 0.f) + fmaxf(pm, 0.f);
    __syncthreads();

    int c = threadIdx.x;
    float acc = 0.f;
#pragma unroll
    for (int rr = 0; rr < HID; rr++) acc += s_h[rr] * w2[c * HID + rr];
    g_catt[b * C + c] = 1.f / (1.f + expf(-acc));
}

// ---------------------------------------------------------------------------
// k3: spatial mean/max over channels of x*ch_att. 256 blocks x 128 thr,
// each thread owns 4 pixels (one float4). Traverses x BACKWARD (serpentine:
// reuse L2 lines that k1 left hot at the tail of x).
// ---------------------------------------------------------------------------
__global__ void k_spstats(const float* __restrict__ x) {
    int rb    = (int)gridDim.x - 1 - (int)blockIdx.x;   // reverse block order
    int b     = rb >> 3;
    int chunk = rb & 7;
    int p4    = chunk * 128 + threadIdx.x;              // float4 idx in plane (0..1023)

    __shared__ float sc[C];
    sc[threadIdx.x]       = g_catt[b * C + threadIdx.x];
    sc[threadIdx.x + 128] = g_catt[b * C + threadIdx.x + 128];
    __syncthreads();

    const float4* xp = (const float4*)x + (size_t)b * C * 1024 + p4;
    float4 s = make_float4(0.f, 0.f, 0.f, 0.f);
    float4 m = make_float4(-CUDART_INF_F, -CUDART_INF_F, -CUDART_INF_F, -CUDART_INF_F);
#pragma unroll 4
    for (int c = C - 1; c >= 0; c--) {                  // reverse channels too
        float a  = sc[c];
        float4 v = xp[(size_t)c * 1024];
        float vx = v.x * a, vy = v.y * a, vz = v.z * a, vw = v.w * a;
        s.x += vx; s.y += vy; s.z += vz; s.w += vw;
        m.x = fmaxf(m.x, vx); m.y = fmaxf(m.y, vy);
        m.z = fmaxf(m.z, vz); m.w = fmaxf(m.w, vw);
    }
    const float inv = 1.f / (float)C;
    s.x *= inv; s.y *= inv; s.z *= inv; s.w *= inv;
    ((float4*)g_spavg)[b * 1024 + p4] = s;
    ((float4*)g_spmax)[b * 1024 + p4] = m;
}

// ---------------------------------------------------------------------------
// k4: 7x7 "same" conv over [avg_sp, max_sp] + sigmoid. 128 blocks (4 row-
// chunks per batch) x 256 thr. Weights fully unrolled into registers; pixels
// come from a zero-padded smem tile; 4-wide output blocking.
// ---------------------------------------------------------------------------
__global__ __launch_bounds__(256) void k_conv(const float* __restrict__ w_sp) {
    int blk   = blockIdx.x;
    int b     = blk >> 2;
    int h0    = (blk & 3) * 16;                 // 16 output rows per block

    // padded tile: 22 rows (h0-3..h0+18) x 70 cols, stride 72
    __shared__ float sp[2][22 * 72];

    for (int i = threadIdx.x; i < 2 * 22 * 72; i += 256)
        ((float*)sp)[i] = 0.f;
    __syncthreads();

    for (int idx = threadIdx.x; idx < 22 * 64; idx += 256) {
        int r  = idx >> 6;          // 0..21
        int cx = idx & 63;
        int gh = h0 + r - 3;
        if (gh >= 0 && gh < 64) {
            sp[0][r * 72 + 3 + cx] = g_spavg[b * HW + gh * 64 + cx];
            sp[1][r * 72 + 3 + cx] = g_spmax[b * HW + gh * 64 + cx];
        }
    }

    // weights -> registers (fully unrolled indexing)
    float wr[2][7][7];
#pragma unroll
    for (int i = 0; i < 2; i++)
#pragma unroll
        for (int kh = 0; kh < 7; kh++)
#pragma unroll
            for (int kw = 0; kw < 7; kw++)
                wr[i][kh][kw] = w_sp[i * 49 + kh * 7 + kw];
    __syncthreads();

    int hl = threadIdx.x >> 4;          // 0..15 local row
    int w0 = (threadIdx.x & 15) * 4;    // 4 consecutive outputs
    float acc[4] = {0.f, 0.f, 0.f, 0.f};
#pragma unroll
    for (int i = 0; i < 2; i++) {
#pragma unroll
        for (int kh = 0; kh < 7; kh++) {
            const float* row = &sp[i][(hl + kh) * 72 + w0];
            float v[10];
#pragma unroll
            for (int t = 0; t < 10; t++) v[t] = row[t];
#pragma unroll
            for (int kw = 0; kw < 7; kw++) {
                float w = wr[i][kh][kw];
                acc[0] += v[kw]     * w;
                acc[1] += v[kw + 1] * w;
                acc[2] += v[kw + 2] * w;
                acc[3] += v[kw + 3] * w;
            }
        }
    }
    int base = b * HW + (h0 + hl) * 64 + w0;
#pragma unroll
    for (int j = 0; j < 4; j++)
        g_asig[base + j] = 1.f / (1.f + expf(-acc[j]));
}

// ---------------------------------------------------------------------------
// k5: out = x * ch_att * sigmoid(att). 32768 blocks x 256 thr, one float4
// each. Reads x FORWARD (k3 ended at address 0 -> hot). Streaming stores
// (__stcs) so the 134MB output write doesn't evict x from L2.
// ---------------------------------------------------------------------------
__global__ void k_final(const float* __restrict__ x, float* __restrict__ out) {
    int idx   = blockIdx.x * 256 + threadIdx.x;   // float4 index, < 8388608
    int plane = idx >> 10;                        // b*C + c
    int p4    = idx & 1023;
    int b     = plane >> 8;

    float  catt = g_catt[plane];
    float4 v    = ((const float4*)x)[idx];
    float4 a    = ((const float4*)g_asig)[b * 1024 + p4];
    float4 o;
    o.x = v.x * catt * a.x;
    o.y = v.y * catt * a.y;
    o.z = v.z * catt * a.z;
    o.w = v.w * catt * a.w;
    __stcs((float4*)out + idx, o);
}

// ---------------------------------------------------------------------------
extern "C" void kernel_launch(void* const* d_in, const int* in_sizes, int n_in,
                              void* d_out, int out_size) {
    const float* x    = (const float*)d_in[0];   // [32,256,64,64]
    const float* w1   = (const float*)d_in[1];   // [16,256]
    const float* w2   = (const float*)d_in[2];   // [256,16]
    const float* w_sp = (const float*)d_in[3];   // [1,2,7,7]
    float* out = (float*)d_out;

    k_chanstats<<<B * C, 256>>>(x);
    k_mlp      <<<B, 256>>>(w1, w2);
    k_spstats  <<<B * 8, 128>>>(x);
    k_conv     <<<B * 4, 256>>>(w_sp);
    k_final    <<<(B * C * HW) / 4 / 256, 256>>>(x, out);
}

// round 2
// speedup vs baseline: 1.5935x; 1.5935x over previous
#include <cuda_runtime.h>
#include <math_constants.h>

#define B   32
#define C   256
#define HW  4096          // 64*64
#define HID 16

// scratch (allocation-free rule: __device__ globals); float4 for alignment
__device__ float  g_avg [B*C];
__device__ float  g_max [B*C];
__device__ float  g_catt[B*C];
__device__ float4 g_spavg4[B*1024];
__device__ float4 g_spmax4[B*1024];
__device__ float4 g_asig4 [B*1024];

// ---------------------------------------------------------------------------
// k1: per-(b,c) mean & max over 4096 pixels. 8192 blocks x 256 thr, float4.
// Reads x FORWARD.
// ---------------------------------------------------------------------------
__global__ void k_chanstats(const float* __restrict__ x) {
    int bc = blockIdx.x;                       // 0..8191
    const float4* xp = (const float4*)x + (size_t)bc * 1024;
    float s = 0.f, m = -CUDART_INF_F;
#pragma unroll
    for (int k = 0; k < 4; k++) {
        float4 v = xp[k * 256 + threadIdx.x];
        s += (v.x + v.y) + (v.z + v.w);
        m = fmaxf(m, fmaxf(fmaxf(v.x, v.y), fmaxf(v.z, v.w)));
    }
#pragma unroll
    for (int off = 16; off; off >>= 1) {
        s += __shfl_down_sync(0xffffffffu, s, off);
        m = fmaxf(m, __shfl_down_sync(0xffffffffu, m, off));
    }
    __shared__ float ss[8], sm[8];
    if ((threadIdx.x & 31) == 0) { ss[threadIdx.x >> 5] = s; sm[threadIdx.x >> 5] = m; }
    __syncthreads();
    if (threadIdx.x == 0) {
        float S = 0.f, M = -CUDART_INF_F;
#pragma unroll
        for (int i = 0; i < 8; i++) { S += ss[i]; M = fmaxf(M, sm[i]); }
        g_avg[bc] = S * (1.f / 4096.f);
        g_max[bc] = M;
    }
}

// ---------------------------------------------------------------------------
// k2: channel MLP + sigmoid. 32 blocks x 256 thr. Tiny.
// ---------------------------------------------------------------------------
__global__ void k_mlp(const float* __restrict__ w1, const float* __restrict__ w2) {
    int b = blockIdx.x;
    __shared__ float s_avg[C], s_mx[C], s_h[HID];
    s_avg[threadIdx.x] = g_avg[b * C + threadIdx.x];
    s_mx [threadIdx.x] = g_max[b * C + threadIdx.x];
    __syncthreads();

    int r    = threadIdx.x >> 4;   // hidden unit 0..15
    int lane = threadIdx.x & 15;
    float pa = 0.f, pm = 0.f;
#pragma unroll
    for (int j = 0; j < 16; j++) {
        int c = lane + j * 16;
        float w = w1[r * C + c];
        pa += w * s_avg[c];
        pm += w * s_mx[c];
    }
#pragma unroll
    for (int off = 8; off; off >>= 1) {
        pa += __shfl_down_sync(0xffffffffu, pa, off, 16);
        pm += __shfl_down_sync(0xffffffffu, pm, off, 16);
    }
    if (lane == 0) s_h[r] = fmaxf(pa, 0.f) + fmaxf(pm, 0.f);
    __syncthreads();

    int c = threadIdx.x;
    float acc = 0.f;
#pragma unroll
    for (int rr = 0; rr < HID; rr++) acc += s_h[rr] * w2[c * HID + rr];
    g_catt[b * C + c] = 1.f / (1.f + expf(-acc));
}

// ---------------------------------------------------------------------------
// k3: spatial mean/max over channels of x*ch_att.
// 1024 blocks x 256 thr. Block = (batch, 32-float4 pixel group).
// Thread = (pixel float4, 1-of-8 channel split of 32 channels).
// Reverse block order + descending channels (serpentine L2 reuse vs k1).
// ---------------------------------------------------------------------------
__global__ __launch_bounds__(256) void k_spstats(const float* __restrict__ x) {
    int rb    = (int)gridDim.x - 1 - (int)blockIdx.x;  // reversed
    int b     = rb >> 5;
    int chunk = rb & 31;
    int lane  = threadIdx.x & 31;          // pixel float4 within group
    int cs    = threadIdx.x >> 5;          // channel split 0..7
    int p4    = chunk * 32 + lane;         // float4 idx in plane (0..1023)

    __shared__ float sc[C];
    sc[threadIdx.x] = g_catt[b * C + threadIdx.x];
    __syncthreads();

    const float4* xp = (const float4*)x + (size_t)b * C * 1024 + p4;
    float4 s = make_float4(0.f, 0.f, 0.f, 0.f);
    float4 m = make_float4(-CUDART_INF_F, -CUDART_INF_F, -CUDART_INF_F, -CUDART_INF_F);
#pragma unroll 8
    for (int j = 31; j >= 0; j--) {                    // descending channels
        int c    = cs * 32 + j;
        float a  = sc[c];
        float4 v = xp[(size_t)c * 1024];
        float vx = v.x * a, vy = v.y * a, vz = v.z * a, vw = v.w * a;
        s.x += vx; s.y += vy; s.z += vz; s.w += vw;
        m.x = fmaxf(m.x, vx); m.y = fmaxf(m.y, vy);
        m.z = fmaxf(m.z, vz); m.w = fmaxf(m.w, vw);
    }

    __shared__ float4 rs[8][32], rm[8][32];
    rs[cs][lane] = s; rm[cs][lane] = m;
    __syncthreads();
    if (threadIdx.x < 32) {
        float4 S = rs[0][lane], M = rm[0][lane];
#pragma unroll
        for (int i = 1; i < 8; i++) {
            float4 a4 = rs[i][lane], b4 = rm[i][lane];
            S.x += a4.x; S.y += a4.y; S.z += a4.z; S.w += a4.w;
            M.x = fmaxf(M.x, b4.x); M.y = fmaxf(M.y, b4.y);
            M.z = fmaxf(M.z, b4.z); M.w = fmaxf(M.w, b4.w);
        }
        const float inv = 1.f / (float)C;
        S.x *= inv; S.y *= inv; S.z *= inv; S.w *= inv;
        g_spavg4[b * 1024 + p4] = S;
        g_spmax4[b * 1024 + p4] = M;
    }
}

// ---------------------------------------------------------------------------
// k4: 7x7 "same" conv over [avg_sp, max_sp] + sigmoid.
// 256 blocks (32 batches x 8 row-chunks of 8 rows) x 512 thr, one output
// pixel per thread. 14x72 zero-padded smem tile per channel.
// ---------------------------------------------------------------------------
__global__ __launch_bounds__(512) void k_conv(const float* __restrict__ w_sp) {
    int blk = blockIdx.x;
    int b   = blk >> 3;
    int h0  = (blk & 7) * 8;                   // 8 output rows

    __shared__ float sp[2][14 * 72];           // rows h0-3..h0+10, cols pad 3

    for (int i = threadIdx.x; i < 2 * 14 * 72; i += 512)
        ((float*)sp)[i] = 0.f;
    __syncthreads();

    const float* spavg = (const float*)g_spavg4;
    const float* spmax = (const float*)g_spmax4;
    for (int idx = threadIdx.x; idx < 14 * 64; idx += 512) {
        int r  = idx >> 6;          // 0..13
        int cx = idx & 63;
        int gh = h0 + r - 3;
        if (gh >= 0 && gh < 64) {
            sp[0][r * 72 + 3 + cx] = spavg[b * HW + gh * 64 + cx];
            sp[1][r * 72 + 3 + cx] = spmax[b * HW + gh * 64 + cx];
        }
    }

    float wr[2][7][7];
#pragma unroll
    for (int i = 0; i < 2; i++)
#pragma unroll
        for (int kh = 0; kh < 7; kh++)
#pragma unroll
            for (int kw = 0; kw < 7; kw++)
                wr[i][kh][kw] = w_sp[i * 49 + kh * 7 + kw];
    __syncthreads();

    int hl = threadIdx.x >> 6;      // 0..7 local row
    int wx = threadIdx.x & 63;      // 0..63 col
    float acc = 0.f;
#pragma unroll
    for (int i = 0; i < 2; i++)
#pragma unroll
        for (int kh = 0; kh < 7; kh++) {
            const float* row = &sp[i][(hl + kh) * 72 + wx];
#pragma unroll
            for (int kw = 0; kw < 7; kw++)
                acc += row[kw] * wr[i][kh][kw];
        }
    ((float*)g_asig4)[b * HW + (h0 + hl) * 64 + wx] = 1.f / (1.f + expf(-acc));
}

// ---------------------------------------------------------------------------
// k5: out = x * ch_att * sigmoid(att). 32768 blocks x 256 thr, one float4
// each. Forward read (k3 ended at addr 0 -> hot); streaming store.
// ---------------------------------------------------------------------------
__global__ void k_final(const float* __restrict__ x, float* __restrict__ out) {
    int idx   = blockIdx.x * 256 + threadIdx.x;   // float4 index
    int plane = idx >> 10;                        // b*C + c
    int p4    = idx & 1023;
    int b     = plane >> 8;

    float  catt = g_catt[plane];
    float4 v    = ((const float4*)x)[idx];
    float4 a    = g_asig4[b * 1024 + p4];
    float4 o;
    o.x = v.x * catt * a.x;
    o.y = v.y * catt * a.y;
    o.z = v.z * catt * a.z;
    o.w = v.w * catt * a.w;
    __stcs((float4*)out + idx, o);
}

// ---------------------------------------------------------------------------
extern "C" void kernel_launch(void* const* d_in, const int* in_sizes, int n_in,
                              void* d_out, int out_size) {
    const float* x    = (const float*)d_in[0];   // [32,256,64,64]
    const float* w1   = (const float*)d_in[1];   // [16,256]
    const float* w2   = (const float*)d_in[2];   // [256,16]
    const float* w_sp = (const float*)d_in[3];   // [1,2,7,7]
    float* out = (float*)d_out;

    k_chanstats<<<B * C, 256>>>(x);
    k_mlp      <<<B, 256>>>(w1, w2);
    k_spstats  <<<B * 32, 256>>>(x);
    k_conv     <<<B * 8, 512>>>(w_sp);
    k_final    <<<(B * C * HW) / 4 / 256, 256>>>(x, out);
}